// round 2
// baseline (speedup 1.0000x reference)
#include <cuda_runtime.h>
#include <math.h>

// Problem constants
constexpr int kB   = 64;
constexpr int kIn  = 1024;
constexpr int kOut = 1024;
constexpr int kE   = 8;
constexpr int kH   = 8;

// Scratch (no allocations allowed — device globals)
__device__ float g_c[kB * kE];                    // per-sample expert coefficients
__device__ float g_part[kE * kB * kOut];          // 2 MB: c-scaled per-expert partials

// ---------------------------------------------------------------------------
// Kernel 1: scalar attention pipeline -> c[b][e] = sum_f att[b,f]*align[f,e]
// ---------------------------------------------------------------------------
__global__ void prep_kernel(const float* __restrict__ x,
                            const float* __restrict__ align_conv,
                            const float* __restrict__ W_ih,
                            const float* __restrict__ b_ih,
                            const float* __restrict__ b_hh,
                            const float* __restrict__ W_att,
                            const float* __restrict__ b_att) {
    const int b   = blockIdx.x;
    const int tid = threadIdx.x;

    float s = 0.f;
    for (int i = tid; i < kIn; i += blockDim.x) s += x[b * kIn + i];
    #pragma unroll
    for (int off = 16; off; off >>= 1) s += __shfl_down_sync(0xffffffffu, s, off);

    __shared__ float red[4];
    if ((tid & 31) == 0) red[tid >> 5] = s;
    __syncthreads();

    if (tid == 0) {
        float tot = red[0] + red[1] + red[2] + red[3];
        float p = tot * (1.f / (float)kIn);

        float r[kH];
        #pragma unroll
        for (int j = 0; j < kH; j++) {
            float h = tanhf(p * W_ih[j] + b_ih[j] + b_hh[j]);  // h0=0 -> W_hh drops
            r[j] = fmaxf(h, 0.f);
        }
        float logits[kE];
        float mx = -1e30f;
        #pragma unroll
        for (int e = 0; e < kE; e++) {
            float l = b_att[e];
            #pragma unroll
            for (int j = 0; j < kH; j++) l += r[j] * W_att[e * kH + j];
            logits[e] = l;
            mx = fmaxf(mx, l);
        }
        float att[kE];
        float se = 0.f;
        #pragma unroll
        for (int e = 0; e < kE; e++) { att[e] = expf(logits[e] - mx); se += att[e]; }
        float inv = 1.f / se;
        #pragma unroll
        for (int e = 0; e < kE; e++) {
            float c = 0.f;
            #pragma unroll
            for (int f = 0; f < kE; f++) c += (att[f] * inv) * align_conv[f * kE + e];
            g_c[b * kE + e] = c;
        }
    }
}

// ---------------------------------------------------------------------------
// Kernel 2: per-expert GEMM partials, f32x2 packed FMA over K-pairs.
// grid (16 o-tiles, 8 experts), 256 threads. Block tile 64b x 64o, thread 4x4.
// ---------------------------------------------------------------------------
__global__ __launch_bounds__(256, 1)
void gemm_kernel(const float* __restrict__ x, const float* __restrict__ w) {
    const int e   = blockIdx.y;
    const int o0  = blockIdx.x * 64;
    const int tid = threadIdx.x;
    const int tx  = tid & 15;   // o group: o = o0 + tx*4 + c
    const int ty  = tid >> 4;   // b group: b = ty*4 + r

    __shared__ float xs[64 * 32];   // [b][i]  8 KB, K-contiguous
    __shared__ float ws[64 * 32];   // [o][i]  8 KB, K-contiguous, slot-swizzled

    unsigned long long acc[4][4];   // f32x2 accumulators over K-pairs
    #pragma unroll
    for (int r = 0; r < 4; r++)
        #pragma unroll
        for (int c = 0; c < 4; c++) acc[r][c] = 0ull;

    const float4* xg = reinterpret_cast<const float4*>(x);
    const float4* wg = reinterpret_cast<const float4*>(w);
    float4* xs4 = reinterpret_cast<float4*>(xs);
    float4* ws4 = reinterpret_cast<float4*>(ws);
    const ulonglong2* xsu = reinterpret_cast<const ulonglong2*>(xs);
    const ulonglong2* wsu = reinterpret_cast<const ulonglong2*>(ws);

    const int wbase4 = (e * kOut + o0) * (kIn / 4);   // float4 index of w[e][o0][0]

    for (int ic = 0; ic < kIn; ic += 32) {
        __syncthreads();
        #pragma unroll
        for (int k = 0; k < 2; k++) {
            int j   = tid + k * 256;      // 0..511
            int row = j >> 3;             // 0..63
            int g   = j & 7;              // float4 slot within 32-float chunk
            xs4[row * 8 + g] = xg[row * (kIn / 4) + (ic >> 2) + g];
            ws4[row * 8 + (g ^ ((row >> 2) & 7))] =
                wg[wbase4 + row * (kIn / 4) + (ic >> 2) + g];
        }
        __syncthreads();

        #pragma unroll
        for (int q = 0; q < 8; q++) {
            ulonglong2 xq[4], wq[4];
            const int sq = q ^ (tx & 7);   // matches store swizzle: (o>>2)&7 == tx&7
            #pragma unroll
            for (int r = 0; r < 4; r++) xq[r] = xsu[(ty * 4 + r) * 8 + q];
            #pragma unroll
            for (int c = 0; c < 4; c++) wq[c] = wsu[(tx * 4 + c) * 8 + sq];
            #pragma unroll
            for (int r = 0; r < 4; r++)
                #pragma unroll
                for (int c = 0; c < 4; c++) {
                    asm("fma.rn.f32x2 %0, %1, %2, %0;"
                        : "+l"(acc[r][c]) : "l"(xq[r].x), "l"(wq[c].x));
                    asm("fma.rn.f32x2 %0, %1, %2, %0;"
                        : "+l"(acc[r][c]) : "l"(xq[r].y), "l"(wq[c].y));
                }
        }
    }

    // Epilogue: horizontal add, scale by c[b,e], store per-expert partial.
    #pragma unroll
    for (int r = 0; r < 4; r++) {
        const int b = ty * 4 + r;
        const float s = g_c[b * kE + e];
        float4 outv;
        float* po = &outv.x;
        #pragma unroll
        for (int c = 0; c < 4; c++) {
            float2 f;
            f = *reinterpret_cast<float2*>(&acc[r][c]);
            po[c] = s * (f.x + f.y);
        }
        reinterpret_cast<float4*>(g_part)[
            (e * kB * kOut + b * kOut + o0 + tx * 4) >> 2] = outv;
    }
}

// ---------------------------------------------------------------------------
// Kernel 3: reduce the 8 expert partials into d_out.
// ---------------------------------------------------------------------------
__global__ void reduce_kernel(float* __restrict__ out) {
    const int idx = blockIdx.x * blockDim.x + threadIdx.x;   // 0..65535 (float4 units: use vec)
    float4 s = make_float4(0.f, 0.f, 0.f, 0.f);
    const float4* p = reinterpret_cast<const float4*>(g_part);
    #pragma unroll
    for (int e = 0; e < kE; e++) {
        float4 v = p[e * (kB * kOut / 4) + idx];
        s.x += v.x; s.y += v.y; s.z += v.z; s.w += v.w;
    }
    reinterpret_cast<float4*>(out)[idx] = s;
}

// ---------------------------------------------------------------------------
extern "C" void kernel_launch(void* const* d_in, const int* in_sizes, int n_in,
                              void* d_out, int out_size) {
    const float* x          = (const float*)d_in[0];
    const float* weight     = (const float*)d_in[1];
    const float* align_conv = (const float*)d_in[2];
    const float* W_ih       = (const float*)d_in[3];
    // d_in[4] = W_hh — unused (h0 = 0)
    const float* b_ih       = (const float*)d_in[5];
    const float* b_hh       = (const float*)d_in[6];
    const float* W_att      = (const float*)d_in[7];
    const float* b_att      = (const float*)d_in[8];
    float* out = (float*)d_out;

    prep_kernel<<<kB, 128>>>(x, align_conv, W_ih, b_ih, b_hh, W_att, b_att);
    gemm_kernel<<<dim3(16, 8), 256>>>(x, weight);
    reduce_kernel<<<(kB * kOut / 4) / 256, 256>>>(out);
}

// round 4
// speedup vs baseline: 2.0440x; 2.0440x over previous
#include <cuda_runtime.h>
#include <cuda_bf16.h>
#include <math.h>
#include <stdint.h>

constexpr int kB   = 64;
constexpr int kIn  = 1024;
constexpr int kOut = 1024;
constexpr int kE   = 8;
constexpr int kH   = 8;

__device__ float g_part[kE * kB * kOut];   // 2 MB per-expert scaled partials

// ---------------------------------------------------------------------------
// helpers
// ---------------------------------------------------------------------------
__device__ __forceinline__ uint32_t smem_u32(const void* p) {
    uint32_t a;
    asm("{ .reg .u64 t; cvta.to.shared.u64 t, %1; cvt.u32.u64 %0, t; }"
        : "=r"(a) : "l"(p));
    return a;
}
__device__ __forceinline__ uint32_t swz(uint32_t off) {   // SW128 (Swizzle<3,4,3>)
    return off ^ ((off >> 3) & 0x70);
}
__device__ __forceinline__ void sts64(uint32_t addr, uint2 v) {
    asm volatile("st.shared.v2.u32 [%0], {%1,%2};" :: "r"(addr), "r"(v.x), "r"(v.y));
}
__device__ __forceinline__ void ldsm4(uint32_t* r, uint32_t addr) {
    asm volatile("ldmatrix.sync.aligned.m8n8.x4.shared.b16 {%0,%1,%2,%3}, [%4];"
                 : "=r"(r[0]), "=r"(r[1]), "=r"(r[2]), "=r"(r[3]) : "r"(addr));
}
__device__ __forceinline__ void mma16816(float* d, const uint32_t* a,
                                         uint32_t b0, uint32_t b1) {
    asm volatile(
        "mma.sync.aligned.m16n8k16.row.col.f32.bf16.bf16.f32 "
        "{%0,%1,%2,%3}, {%4,%5,%6,%7}, {%8,%9}, {%0,%1,%2,%3};"
        : "+f"(d[0]), "+f"(d[1]), "+f"(d[2]), "+f"(d[3])
        : "r"(a[0]), "r"(a[1]), "r"(a[2]), "r"(a[3]), "r"(b0), "r"(b1));
}
// split float4 into bf16 hi pairs + bf16 residual pairs (k-contiguous packing)
__device__ __forceinline__ void split4(float4 f, uint2& h, uint2& l) {
    __nv_bfloat162 h01 = __floats2bfloat162_rn(f.x, f.y);
    __nv_bfloat162 h23 = __floats2bfloat162_rn(f.z, f.w);
    float a0 = __bfloat162float(h01.x), a1 = __bfloat162float(h01.y);
    float a2 = __bfloat162float(h23.x), a3 = __bfloat162float(h23.y);
    __nv_bfloat162 l01 = __floats2bfloat162_rn(f.x - a0, f.y - a1);
    __nv_bfloat162 l23 = __floats2bfloat162_rn(f.z - a2, f.w - a3);
    h = make_uint2(*reinterpret_cast<uint32_t*>(&h01), *reinterpret_cast<uint32_t*>(&h23));
    l = make_uint2(*reinterpret_cast<uint32_t*>(&l01), *reinterpret_cast<uint32_t*>(&l23));
}

// ---------------------------------------------------------------------------
// GEMM + fused prep. 128 CTAs x 256 threads. CTA tile m64(eo) x n64(b), KC=64.
// smem: 2 stages x (A_hi 8K | A_lo 8K | B_hi 8K | B_lo 8K) = 64 KB.
// ---------------------------------------------------------------------------
constexpr int STAGE = 32768;
constexpr int AH = 0, AL = 8192, BH = 16384, BL = 24576;
constexpr int SMEM_TOTAL = 2 * STAGE;      // 65536
constexpr int CS_OFF = 57344;              // inside stage1 BL, free at epilogue

__global__ __launch_bounds__(256, 1)
void gemm_kernel(const float* __restrict__ x, const float* __restrict__ w,
                 const float* __restrict__ align_conv,
                 const float* __restrict__ W_ih, const float* __restrict__ b_ih,
                 const float* __restrict__ b_hh, const float* __restrict__ W_att,
                 const float* __restrict__ b_att) {
    extern __shared__ char smem[];
    const uint32_t sbase = smem_u32(smem);
    const int tid  = threadIdx.x;
    const int lane = tid & 31;
    const int wid  = tid >> 5;
    const int wm   = wid & 1;        // m half (32 rows)
    const int wn   = wid >> 1;       // n quarter (16 cols)
    const int m0   = blockIdx.x * 64;
    const int e    = blockIdx.x >> 4;        // 16 CTAs per expert
    const int ob   = m0 & 1023;

    float acc[2][2][4];
    #pragma unroll
    for (int i = 0; i < 2; i++)
        #pragma unroll
        for (int j = 0; j < 2; j++)
            #pragma unroll
            for (int c = 0; c < 4; c++) acc[i][j][c] = 0.f;

    float sx[4] = {0.f, 0.f, 0.f, 0.f};

    const float4* wg = reinterpret_cast<const float4*>(w);
    const float4* xg = reinterpret_cast<const float4*>(x);
    int rw[4], cw[4];
    #pragma unroll
    for (int q = 0; q < 4; q++) { int j = tid + q * 256; rw[q] = j >> 4; cw[q] = j & 15; }

    float4 wr[4], xr[4];
    #pragma unroll
    for (int q = 0; q < 4; q++) {
        wr[q] = wg[(m0 + rw[q]) * 256 + cw[q]];
        xr[q] = xg[rw[q] * 256 + cw[q]];
    }

    for (int ch = 0; ch < 16; ch++) {
        const uint32_t sb = sbase + (ch & 1) * STAGE;

        // convert + swizzled STS (also fold x row-sums for the fused prep)
        #pragma unroll
        for (int q = 0; q < 4; q++) {
            const uint32_t so = swz((uint32_t)(rw[q] * 128 + cw[q] * 8));
            uint2 h, l;
            split4(wr[q], h, l);
            sts64(sb + AH + so, h);
            sts64(sb + AL + so, l);
        }
        #pragma unroll
        for (int q = 0; q < 4; q++) {
            sx[q] += xr[q].x + xr[q].y + xr[q].z + xr[q].w;
            const uint32_t so = swz((uint32_t)(rw[q] * 128 + cw[q] * 8));
            uint2 h, l;
            split4(xr[q], h, l);
            sts64(sb + BH + so, h);
            sts64(sb + BL + so, l);
        }
        __syncthreads();

        if (ch < 15) {
            const int kc = (ch + 1) * 16;
            #pragma unroll
            for (int q = 0; q < 4; q++) {
                wr[q] = wg[(m0 + rw[q]) * 256 + kc + cw[q]];
                xr[q] = xg[rw[q] * 256 + kc + cw[q]];
            }
        }

        // 4 k16 steps: 24 LDSM + 48 HMMA per warp per chunk
        #pragma unroll
        for (int kk = 0; kk < 4; kk++) {
            const uint32_t kb = kk * 32;
            const uint32_t arow = (uint32_t)(wm * 32 + (lane & 15));
            const uint32_t akb  = kb + ((lane >> 4) << 4);
            uint32_t ah0[4], ah1[4], al0[4], al1[4], bh[4], bl[4];
            ldsm4(ah0, sb + AH + swz(arow * 128 + akb));
            ldsm4(ah1, sb + AH + swz((arow + 16) * 128 + akb));
            ldsm4(al0, sb + AL + swz(arow * 128 + akb));
            ldsm4(al1, sb + AL + swz((arow + 16) * 128 + akb));
            const uint32_t brow = (uint32_t)(wn * 16 + ((lane >> 4) << 3) + (lane & 7));
            const uint32_t bkb  = kb + (((lane >> 3) & 1) << 4);
            ldsm4(bh, sb + BH + swz(brow * 128 + bkb));
            ldsm4(bl, sb + BL + swz(brow * 128 + bkb));

            #pragma unroll
            for (int ni = 0; ni < 2; ni++) {
                mma16816(acc[0][ni], ah0, bh[2 * ni], bh[2 * ni + 1]);
                mma16816(acc[0][ni], ah0, bl[2 * ni], bl[2 * ni + 1]);
                mma16816(acc[0][ni], al0, bh[2 * ni], bh[2 * ni + 1]);
                mma16816(acc[1][ni], ah1, bh[2 * ni], bh[2 * ni + 1]);
                mma16816(acc[1][ni], ah1, bl[2 * ni], bl[2 * ni + 1]);
                mma16816(acc[1][ni], al1, bh[2 * ni], bh[2 * ni + 1]);
            }
        }
    }

    // ---------------- fused prep: c[b, e] for this CTA's expert ----------------
    float* sums = reinterpret_cast<float*>(smem);              // [64][16]
    #pragma unroll
    for (int q = 0; q < 4; q++) sums[rw[q] * 16 + (tid & 15)] = sx[q];
    __syncthreads();

    float* cs = reinterpret_cast<float*>(smem + CS_OFF);       // [64]
    if (tid < 64) {
        float s = 0.f;
        #pragma unroll
        for (int i = 0; i < 16; i++) s += sums[tid * 16 + i];
        const float pm = s * (1.f / (float)kIn);
        float r[kH];
        #pragma unroll
        for (int j = 0; j < kH; j++)
            r[j] = fmaxf(tanhf(fmaf(pm, W_ih[j], b_ih[j] + b_hh[j])), 0.f);
        float logits[kE], mx = -1e30f;
        #pragma unroll
        for (int f = 0; f < kE; f++) {
            float l = b_att[f];
            #pragma unroll
            for (int j = 0; j < kH; j++) l = fmaf(r[j], W_att[f * kH + j], l);
            logits[f] = l;
            mx = fmaxf(mx, l);
        }
        float se = 0.f, att[kE];
        #pragma unroll
        for (int f = 0; f < kE; f++) { att[f] = expf(logits[f] - mx); se += att[f]; }
        const float inv = 1.f / se;
        float c = 0.f;
        #pragma unroll
        for (int f = 0; f < kE; f++) c = fmaf(att[f] * inv, align_conv[f * kE + e], c);
        cs[tid] = c;
    }
    __syncthreads();

    // ---------------- epilogue: transpose to [b][o] via smem, scaled STG ------
    float* tr = reinterpret_cast<float*>(smem);                // [64 b][68 pad]
    #pragma unroll
    for (int mi = 0; mi < 2; mi++)
        #pragma unroll
        for (int ni = 0; ni < 2; ni++) {
            const int r0 = wm * 32 + mi * 16 + (lane >> 2);
            const int c0 = wn * 16 + ni * 8 + (lane & 3) * 2;
            tr[c0 * 68 + r0]            = acc[mi][ni][0];
            tr[(c0 + 1) * 68 + r0]      = acc[mi][ni][1];
            tr[c0 * 68 + r0 + 8]        = acc[mi][ni][2];
            tr[(c0 + 1) * 68 + r0 + 8]  = acc[mi][ni][3];
        }
    __syncthreads();

    {
        const int b = tid >> 2;
        const float s = cs[b];
        #pragma unroll
        for (int it = 0; it < 4; it++) {
            const int o4 = (tid & 3) + it * 4;
            float4 v = *reinterpret_cast<const float4*>(&tr[b * 68 + o4 * 4]);
            v.x *= s; v.y *= s; v.z *= s; v.w *= s;
            *reinterpret_cast<float4*>(
                &g_part[e * (kB * kOut) + b * kOut + ob + o4 * 4]) = v;
        }
    }
}

// ---------------------------------------------------------------------------
// reduce the 8 expert partials into d_out
// ---------------------------------------------------------------------------
__global__ void reduce_kernel(float* __restrict__ out) {
    const int idx = blockIdx.x * blockDim.x + threadIdx.x;
    float4 s = make_float4(0.f, 0.f, 0.f, 0.f);
    const float4* p = reinterpret_cast<const float4*>(g_part);
    #pragma unroll
    for (int e = 0; e < kE; e++) {
        float4 v = p[e * (kB * kOut / 4) + idx];
        s.x += v.x; s.y += v.y; s.z += v.z; s.w += v.w;
    }
    reinterpret_cast<float4*>(out)[idx] = s;
}

// ---------------------------------------------------------------------------
extern "C" void kernel_launch(void* const* d_in, const int* in_sizes, int n_in,
                              void* d_out, int out_size) {
    const float* x          = (const float*)d_in[0];
    const float* weight     = (const float*)d_in[1];
    const float* align_conv = (const float*)d_in[2];
    const float* W_ih       = (const float*)d_in[3];
    // d_in[4] = W_hh — unused (h0 = 0)
    const float* b_ih       = (const float*)d_in[5];
    const float* b_hh       = (const float*)d_in[6];
    const float* W_att      = (const float*)d_in[7];
    const float* b_att      = (const float*)d_in[8];
    float* out = (float*)d_out;

    cudaFuncSetAttribute(gemm_kernel, cudaFuncAttributeMaxDynamicSharedMemorySize,
                         SMEM_TOTAL);

    gemm_kernel<<<128, 256, SMEM_TOTAL>>>(x, weight, align_conv,
                                          W_ih, b_ih, b_hh, W_att, b_att);
    reduce_kernel<<<(kB * kOut / 4) / 256, 256>>>(out);
}